// round 14
// baseline (speedup 1.0000x reference)
#include <cuda_runtime.h>
#include <cuda_fp16.h>
#include <cstdint>
#include <math.h>

#define HDIM   512
#define BDIM   512
#define GDIM   2048
#define NSTEPS 30
#define BH     (BDIM * HDIM)
#define BH2    (BDIM * 256)          // half2 per [512,512] plane
#define WPL2   (2048 * 256)          // half2 per [2048,512] weight plane
#define WSZF   ((size_t)GDIM * HDIM) // fp32 weight plane elems

__device__ __align__(1024) __half2 g_w16ih[60 * WPL2];   // 125.8 MB
__device__ __align__(1024) __half2 g_w16hh[60 * WPL2];   // 125.8 MB
__device__ __align__(1024) __half2 g_x16[NSTEPS * BH2];  // 15.7 MB
__device__ __align__(1024) __half2 g_h16[4 * BH2];       // [parity][layer], 2 MB

// dependency-exact sync counters (zeroed every replay by zero_state)
__device__ int g_arr_l0[NSTEPS];
__device__ int g_arr_l1[NSTEPS];
__device__ int g_arr_cv[NSTEPS];

#define NJOB  256
#define NCONV 40
#define NCTAS (NJOB + NCONV)        // 296 = 2/SM x 148 SMs (all co-resident)

// ---------------- helpers ----------------
__device__ __forceinline__ uint32_t smem_u32(const void* p) {
    uint32_t a;
    asm("{ .reg .u64 t; cvta.to.shared.u64 t, %1; cvt.u32.u64 %0, t; }" : "=r"(a) : "l"(p));
    return a;
}
#define CP_ASYNC16(dst_u32, src_ptr) \
    asm volatile("cp.async.cg.shared.global [%0], [%1], 16;" \
                 :: "r"(dst_u32), "l"(src_ptr) : "memory")
#define CP_COMMIT() asm volatile("cp.async.commit_group;" ::: "memory")
#define CP_WAIT1()  asm volatile("cp.async.wait_group 1;" ::: "memory")

__device__ __forceinline__ void mma_f16(float* d,
                                        uint32_t a0, uint32_t a1, uint32_t a2, uint32_t a3,
                                        uint32_t b0, uint32_t b1) {
    asm volatile(
        "mma.sync.aligned.m16n8k16.row.col.f32.f16.f16.f32 "
        "{%0,%1,%2,%3}, {%4,%5,%6,%7}, {%8,%9}, {%0,%1,%2,%3};"
        : "+f"(d[0]), "+f"(d[1]), "+f"(d[2]), "+f"(d[3])
        : "r"(a0), "r"(a1), "r"(a2), "r"(a3), "r"(b0), "r"(b1));
}
__device__ __forceinline__ float fast_sigmoid(float x) {
    return __fdividef(1.0f, 1.0f + __expf(-x));
}
__device__ __forceinline__ float fast_tanh(float x) {
    return 1.0f - __fdividef(2.0f, __expf(2.0f * x) + 1.0f);
}
__device__ __forceinline__ uint32_t pk(float a, float b) {
    __half2 h = __floats2half2_rn(a, b);
    return *reinterpret_cast<uint32_t*>(&h);
}
__device__ __forceinline__ void spin_ge(volatile int* p, int target) {
    while (*p < target) __nanosleep(32);
}

// ---------------- vectorized fp32 -> permuted fp16 chunk converter ----------------
__device__ __forceinline__ void convert_chunk(const float* __restrict__ src,
                                              __half2* __restrict__ dst, int c) {
    const int row = c >> 4, cb = c & 15;
    const float4* s4 = (const float4*)(src + ((size_t)row << 9) + (cb << 5));
    float f[32];
#pragma unroll
    for (int q = 0; q < 8; q++) {
        float4 v = s4[q];
        f[q * 4 + 0] = v.x; f[q * 4 + 1] = v.y; f[q * 4 + 2] = v.z; f[q * 4 + 3] = v.w;
    }
    uint32_t o[16];
#pragma unroll
    for (int p = 0; p < 16; p++) {
        int q = (p & 3) * 4 + (p >> 2);
        o[p] = pk(f[2 * q], f[2 * q + 1]);
    }
    uint4* d4 = (uint4*)(dst + ((size_t)row << 8) + (cb << 4));
#pragma unroll
    for (int v = 0; v < 4; v++)
        d4[v] = make_uint4(o[v * 4], o[v * 4 + 1], o[v * 4 + 2], o[v * 4 + 3]);
}

// ---------------- smem layout (R11/R13-proven) ----------------
#define NSTAGE    6
#define STAGE_B   12288
#define OFF_W     4096
#define SMC_OFF   (NSTAGE * STAGE_B)        // 73728: c tile [64][36] floats
#define BIAS_OFF  (SMC_OFF + 64 * 36 * 4)   // 82944
#define SMEM_BYTES (BIAS_OFF + 512)         // 83456
#define NKB 32
#define CPAD 36
#define CHUNKS_PER_TENSOR 65536

// first-half operand (it<16) is the dependency-free one; second half is the tight edge
__device__ __forceinline__ void issue_stage(uint32_t sb, int s, int it,
                                            const __half2* Af, const __half2* As2,
                                            const __half2* Wf, const __half2* Ws2,
                                            int m0, int j0, int tid) {
    const __half2* Ap = (it < 16) ? Af : As2;
    const __half2* Wp = (it < 16) ? Wf : Ws2;
    const int kk = (it & 15) << 4;
    const uint32_t as = sb + s * STAGE_B;
    const uint32_t ws = as + OFF_W;
    {   // A: 64 rows x 4 chunks, 1/thread
        int row = tid >> 2, u = tid & 3;
        CP_ASYNC16(as + (row << 6) + (u << 4),
                   Ap + (size_t)(m0 + row) * 256 + kk + u * 4);
    }
#pragma unroll
    for (int t2 = 0; t2 < 2; t2++) {    // W: 128 rows x 4 chunks, 2/thread
        int idx = tid + t2 * 256;
        int r = idx >> 2, u = idx & 3;
        int grow = (r & 3) * 512 + j0 + (r >> 2);
        CP_ASYNC16(ws + (r << 6) + (u << 4),
                   Wp + (size_t)grow * 256 + kk + u * 4);
    }
}

__global__ __launch_bounds__(256, 2) void lstm_persistent(
    const float* __restrict__ b_ih, const float* __restrict__ b_hh,
    const float* __restrict__ Wih32, const float* __restrict__ Whh32,
    float* __restrict__ out)
{
    extern __shared__ char smem[];
    const int cta = blockIdx.x;
    const int tid = threadIdx.x;

    // ---------------- converter CTAs: free-running, paced <=6 steps ahead ----------------
    if (cta >= NJOB) {
        const int w = cta - NJOB;
        for (int s = 2; s < NSTEPS; s++) {
            if (tid == 0 && s >= 6) spin_ge(&g_arr_l0[s - 6], 128);
            __syncthreads();
            const float* cIh = Wih32 + (size_t)(s * 2) * WSZF;
            const float* cHh = Whh32 + (size_t)(s * 2) * WSZF;
            __half2* dIh = g_w16ih + (size_t)(s * 2) * WPL2;
            __half2* dHh = g_w16hh + (size_t)(s * 2) * WPL2;
            for (int c = w * 256 + tid; c < 2 * CHUNKS_PER_TENSOR; c += NCONV * 256) {
                if (c < CHUNKS_PER_TENSOR) convert_chunk(cIh, dIh, c);
                else                       convert_chunk(cHh, dHh, c - CHUNKS_PER_TENSOR);
            }
            __threadfence();
            __syncthreads();
            if (tid == 0) atomicAdd(&g_arr_cv[s], 1);
        }
        return;
    }

    // ---------------- job CTAs: fixed (layer, tile) ----------------
    const uint32_t sb = smem_u32(smem);
    const int layer = (cta < 128) ? 0 : 1;
    const int tile = cta & 127;
    const int m0 = (tile >> 4) * 64;
    const int j0 = (tile & 15) * 32;

    const int lane = tid & 31, wid = tid >> 5;
    const int wm = wid & 1;
    const int wn = wid >> 1;
    const int r4 = lane >> 2, u = lane & 3;
    const bool evn = !(u & 1);

    float* smc = (float*)(smem + SMC_OFF);
    float* smb = (float*)(smem + BIAS_OFF);
    float* smh = (float*)smem;

    for (int i = tid; i < 64 * CPAD; i += 256) smc[i] = 0.f;
    __syncthreads();

    const int aoff = ((wm * 32 + r4) << 6) + (u << 4);
    const int boff = ((wn * 32 + r4) << 6) + (u << 4) + OFF_W;

    for (int t = 0; t < NSTEPS; t++) {
        // ---- slack waits at phase top (NOT the tight edge) ----
        if (tid == 0) {
            if (layer == 0) {
                if (t >= 2) spin_ge(&g_arr_l1[t - 2], 128);   // plane-reuse back-pressure
            } else {
                if (t >= 1) spin_ge(&g_arr_l1[t - 1], 128);   // h(l1,t-1): one-phase slack
            }
            spin_ge(&g_arr_cv[t], NCONV);                     // weights step t converted
            __threadfence();
        }
        __syncthreads();

        const int wp = t & 1, rp = wp ^ 1;
        const int widx = t * 2 + layer;
        // first half = dependency-free operand; second half = tight edge
        const __half2 *Af, *As2, *Wf, *Ws2;
        volatile int* midDep = nullptr;
        if (layer == 0) {
            int xt = (t < NSTEPS - 1) ? t : NSTEPS - 2;  // source bug: step 29 reuses x[28]
            Af  = g_x16 + (size_t)xt * BH2;                    // x @ W_ih
            Wf  = g_w16ih + (size_t)widx * WPL2;
            As2 = g_h16 + (size_t)(rp * 2 + 0) * BH2;          // h(l0,t-1) @ W_hh
            Ws2 = g_w16hh + (size_t)widx * WPL2;
            if (t >= 1) midDep = &g_arr_l0[t - 1];
        } else {
            Af  = g_h16 + (size_t)(rp * 2 + 1) * BH2;          // h(l1,t-1) @ W_hh
            Wf  = g_w16hh + (size_t)widx * WPL2;
            As2 = g_h16 + (size_t)(wp * 2 + 0) * BH2;          // h(l0,t) @ W_ih  (tight)
            Ws2 = g_w16ih + (size_t)widx * WPL2;
            midDep = &g_arr_l0[t];
        }
        __half2* h16o = g_h16 + (size_t)(wp * 2 + layer) * BH2;
        float* y   = (layer == 1) ? out + (size_t)t * BH : nullptr;
        float* h32 = (t == NSTEPS - 1) ? out + (size_t)(NSTEPS + layer) * BH : nullptr;

        if (tid < 128) {   // guard load-bearing: smb is 128 floats
            int g = tid >> 5, jj = tid & 31;
            smb[tid] = b_ih[(size_t)widx * GDIM + g * 512 + j0 + jj]
                     + b_hh[(size_t)widx * GDIM + g * 512 + j0 + jj];
        }

        float acc[2][4][4];
#pragma unroll
        for (int mt = 0; mt < 2; mt++)
#pragma unroll
            for (int nt = 0; nt < 4; nt++)
#pragma unroll
                for (int e = 0; e < 4; e++) acc[mt][nt][e] = 0.f;

        issue_stage(sb, 0, 0, Af, As2, Wf, Ws2, m0, j0, tid);
        issue_stage(sb, 1, 1, Af, As2, Wf, Ws2, m0, j0, tid); CP_COMMIT();
        issue_stage(sb, 2, 2, Af, As2, Wf, Ws2, m0, j0, tid);
        issue_stage(sb, 3, 3, Af, As2, Wf, Ws2, m0, j0, tid); CP_COMMIT();

        int s = 0;
        for (int itp = 0; itp < NKB; itp += 2) {
            CP_WAIT1();
            __syncthreads();
            if (itp == 12) {   // about to issue k-blocks 16,17 -> need second operand now
                if (tid == 0 && midDep) { spin_ge(midDep, 128); __threadfence(); }
                __syncthreads();
            }
            if (itp + 4 < NKB) {
                int s4 = s + 4; if (s4 >= NSTAGE) s4 -= NSTAGE;
                int s5 = s4 + 1; if (s5 >= NSTAGE) s5 -= NSTAGE;
                issue_stage(sb, s4, itp + 4, Af, As2, Wf, Ws2, m0, j0, tid);
                issue_stage(sb, s5, itp + 5, Af, As2, Wf, Ws2, m0, j0, tid);
            }
            CP_COMMIT();

#pragma unroll
            for (int h = 0; h < 2; h++) {
                const char* st = smem + (s + h) * STAGE_B;
                uint4 a0lo = *(const uint4*)(st + aoff);
                uint4 a0hi = *(const uint4*)(st + aoff + 512);
                uint4 a1lo = *(const uint4*)(st + aoff + 1024);
                uint4 a1hi = *(const uint4*)(st + aoff + 1536);
#pragma unroll
                for (int nt = 0; nt < 4; nt++) {
                    uint4 bb = *(const uint4*)(st + boff + (nt << 9));
                    mma_f16(acc[0][nt], a0lo.x, a0hi.x, a0lo.y, a0hi.y, bb.x, bb.y);
                    mma_f16(acc[0][nt], a0lo.z, a0hi.z, a0lo.w, a0hi.w, bb.z, bb.w);
                    mma_f16(acc[1][nt], a1lo.x, a1hi.x, a1lo.y, a1hi.y, bb.x, bb.y);
                    mma_f16(acc[1][nt], a1lo.z, a1hi.z, a1lo.w, a1hi.w, bb.z, bb.w);
                }
            }
            s += 2; if (s == NSTAGE) s = 0;
        }

        // ---- fused LSTM cell epilogue (c resident in smem) ----
        __syncthreads();
#pragma unroll
        for (int mt = 0; mt < 2; mt++) {
            const int row = wm * 32 + mt * 16 + r4 + (evn ? 0 : 8);
#pragma unroll
            for (int nt = 0; nt < 4; nt++) {
                float x0 = __shfl_xor_sync(0xFFFFFFFFu, acc[mt][nt][0], 1);
                float x1 = __shfl_xor_sync(0xFFFFFFFFu, acc[mt][nt][1], 1);
                float x2 = __shfl_xor_sync(0xFFFFFFFFu, acc[mt][nt][2], 1);
                float x3 = __shfl_xor_sync(0xFFFFFFFFu, acc[mt][nt][3], 1);
                int jj = wn * 8 + nt * 2 + (u >> 1);
                float vi = (evn ? acc[mt][nt][0] : x2) + smb[jj];
                float vf = (evn ? acc[mt][nt][1] : x3) + smb[32 + jj];
                float vg = (evn ? x0 : acc[mt][nt][2]) + smb[64 + jj];
                float vo = (evn ? x1 : acc[mt][nt][3]) + smb[96 + jj];
                float ii = fast_sigmoid(vi);
                float ff = fast_sigmoid(vf);
                float gg = fast_tanh(vg);
                float oo = fast_sigmoid(vo);
                float cn = ff * smc[row * CPAD + jj] + ii * gg;
                float hn = oo * fast_tanh(cn);
                smc[row * CPAD + jj] = cn;
                smh[row * CPAD + jj] = hn;
            }
        }
        __syncthreads();

        for (int i = tid; i < 64 * 32; i += 256) {
            int r = i >> 5, jj = i & 31;
            size_t g = (size_t)(m0 + r) * HDIM + j0 + jj;
            float hv = smh[r * CPAD + jj];
            if (y)   y[g]   = hv;
            if (h32) h32[g] = hv;
        }
        for (int i = tid; i < 64 * 16; i += 256) {
            int r = i >> 4, q = i & 15;
            int pq = (q & 3) * 4 + (q >> 2);
            __half2 hv = __floats2half2_rn(smh[r * CPAD + 2 * q], smh[r * CPAD + 2 * q + 1]);
            h16o[(size_t)(m0 + r) * 256 + (j0 >> 1) + pq] = hv;
        }

        // ---- publish (release) ----
        __threadfence();
        __syncthreads();
        if (tid == 0) atomicAdd(layer == 0 ? &g_arr_l0[t] : &g_arr_l1[t], 1);
    }

    // final c -> output tail
    float* cdst = out + (size_t)(NSTEPS + 2 + layer) * BH;
    for (int i = tid; i < 64 * 32; i += 256) {
        int r = i >> 5, jj = i & 31;
        cdst[(size_t)(m0 + r) * HDIM + j0 + jj] = smc[r * CPAD + jj];
    }
}

// upfront conversions
__global__ __launch_bounds__(256) void conv_chunks(const float* __restrict__ src,
                                                   __half2* __restrict__ dst, int nChunks) {
    int c = blockIdx.x * 256 + threadIdx.x;
    if (c < nChunks) convert_chunk(src, dst, c);
}

__global__ void zero_state() {
    int i = blockIdx.x * 256 + threadIdx.x;
    if (i < 2 * BH2) g_h16[2 * BH2 + i] = __floats2half2_rn(0.f, 0.f);  // parity-1 planes
    if (i < NSTEPS) {
        g_arr_l0[i] = 0;
        g_arr_l1[i] = 0;
        g_arr_cv[i] = (i < 2) ? NCONV : 0;   // steps 0,1 converted upfront
    }
}

// ---------------- host ----------------
extern "C" void kernel_launch(void* const* d_in, const int* in_sizes, int n_in,
                              void* d_out, int out_size)
{
    const float* x    = (const float*)d_in[0];
    const float* W_ih = (const float*)d_in[1];
    const float* W_hh = (const float*)d_in[2];
    const float* b_ih = (const float*)d_in[3];
    const float* b_hh = (const float*)d_in[4];
    float* out = (float*)d_out;

    __half2 *w16ih, *w16hh, *x16;
    cudaGetSymbolAddress((void**)&w16ih, g_w16ih);
    cudaGetSymbolAddress((void**)&w16hh, g_w16hh);
    cudaGetSymbolAddress((void**)&x16,   g_x16);

    cudaFuncSetAttribute(lstm_persistent, cudaFuncAttributeMaxDynamicSharedMemorySize, SMEM_BYTES);

    conv_chunks<<<(NSTEPS * 512 * 16 + 255) / 256, 256>>>(x, x16, NSTEPS * 512 * 16);
    conv_chunks<<<(2 * CHUNKS_PER_TENSOR + 255) / 256, 256>>>(W_ih, w16ih, 2 * CHUNKS_PER_TENSOR);
    conv_chunks<<<(2 * CHUNKS_PER_TENSOR + 255) / 256, 256>>>(W_hh, w16hh, 2 * CHUNKS_PER_TENSOR);
    zero_state<<<(2 * BH2 + 255) / 256, 256>>>();

    lstm_persistent<<<NCTAS, 256, SMEM_BYTES>>>(b_ih, b_hh, W_ih, W_hh, out);
}

// round 15
// speedup vs baseline: 1.0090x; 1.0090x over previous
#include <cuda_runtime.h>
#include <cuda_fp16.h>
#include <cstdint>
#include <math.h>

#define HDIM   512
#define BDIM   512
#define GDIM   2048
#define NSTEPS 30
#define BH     (BDIM * HDIM)
#define BH2    (BDIM * 256)          // half2 per [512,512] plane
#define WPL2   (2048 * 256)          // half2 per [2048,512] weight plane
#define WSZF   ((size_t)GDIM * HDIM) // fp32 weight plane elems

__device__ __align__(1024) __half2 g_w16ih[60 * WPL2];   // 125.8 MB
__device__ __align__(1024) __half2 g_w16hh[60 * WPL2];   // 125.8 MB
__device__ __align__(1024) __half2 g_x16[NSTEPS * BH2];  // 15.7 MB
__device__ __align__(1024) __half2 g_h16[4 * BH2];       // [parity][layer], 2 MB

// dependency-exact sync counters (zeroed every replay by zero_state)
__device__ int g_arr_l0[NSTEPS];
__device__ int g_arr_l1[NSTEPS];
__device__ int g_arr_cv[NSTEPS];

#define NJOB  256
#define NCONV 40
#define NCTAS (NJOB + NCONV)        // 296 = 2/SM x 148 SMs (all co-resident)

// ---------------- helpers ----------------
__device__ __forceinline__ uint32_t smem_u32(const void* p) {
    uint32_t a;
    asm("{ .reg .u64 t; cvta.to.shared.u64 t, %1; cvt.u32.u64 %0, t; }" : "=r"(a) : "l"(p));
    return a;
}
#define CP_ASYNC16(dst_u32, src_ptr) \
    asm volatile("cp.async.cg.shared.global [%0], [%1], 16;" \
                 :: "r"(dst_u32), "l"(src_ptr) : "memory")
#define CP_COMMIT() asm volatile("cp.async.commit_group;" ::: "memory")
#define CP_WAIT1()  asm volatile("cp.async.wait_group 1;" ::: "memory")

__device__ __forceinline__ void stg_cs(float* p, float v) {
    asm volatile("st.global.cs.f32 [%0], %1;" :: "l"(p), "f"(v) : "memory");
}

__device__ __forceinline__ void mma_f16(float* d,
                                        uint32_t a0, uint32_t a1, uint32_t a2, uint32_t a3,
                                        uint32_t b0, uint32_t b1) {
    asm volatile(
        "mma.sync.aligned.m16n8k16.row.col.f32.f16.f16.f32 "
        "{%0,%1,%2,%3}, {%4,%5,%6,%7}, {%8,%9}, {%0,%1,%2,%3};"
        : "+f"(d[0]), "+f"(d[1]), "+f"(d[2]), "+f"(d[3])
        : "r"(a0), "r"(a1), "r"(a2), "r"(a3), "r"(b0), "r"(b1));
}
__device__ __forceinline__ float fast_sigmoid(float x) {
    return __fdividef(1.0f, 1.0f + __expf(-x));
}
__device__ __forceinline__ float fast_tanh(float x) {
    return 1.0f - __fdividef(2.0f, __expf(2.0f * x) + 1.0f);
}
__device__ __forceinline__ uint32_t pk(float a, float b) {
    __half2 h = __floats2half2_rn(a, b);
    return *reinterpret_cast<uint32_t*>(&h);
}
__device__ __forceinline__ void spin_ge(volatile int* p, int target) {
    while (*p < target) __nanosleep(32);
}

// ---------------- vectorized fp32 -> permuted fp16 chunk converter ----------------
__device__ __forceinline__ void convert_chunk(const float* __restrict__ src,
                                              __half2* __restrict__ dst, int c) {
    const int row = c >> 4, cb = c & 15;
    const float4* s4 = (const float4*)(src + ((size_t)row << 9) + (cb << 5));
    float f[32];
#pragma unroll
    for (int q = 0; q < 8; q++) {
        float4 v = s4[q];
        f[q * 4 + 0] = v.x; f[q * 4 + 1] = v.y; f[q * 4 + 2] = v.z; f[q * 4 + 3] = v.w;
    }
    uint32_t o[16];
#pragma unroll
    for (int p = 0; p < 16; p++) {
        int q = (p & 3) * 4 + (p >> 2);
        o[p] = pk(f[2 * q], f[2 * q + 1]);
    }
    uint4* d4 = (uint4*)(dst + ((size_t)row << 8) + (cb << 4));
#pragma unroll
    for (int v = 0; v < 4; v++)
        d4[v] = make_uint4(o[v * 4], o[v * 4 + 1], o[v * 4 + 2], o[v * 4 + 3]);
}

// ---------------- smem layout (R11/R13-proven) ----------------
#define NSTAGE    6
#define STAGE_B   12288
#define OFF_W     4096
#define SMC_OFF   (NSTAGE * STAGE_B)        // 73728: c tile [64][36] floats
#define BIAS_OFF  (SMC_OFF + 64 * 36 * 4)   // 82944
#define SMEM_BYTES (BIAS_OFF + 512)         // 83456
#define NKB 32
#define CPAD 36
#define CHUNKS_PER_TENSOR 65536

__device__ __forceinline__ void issue_stage(uint32_t sb, int s, int it,
                                            const __half2* A1, const __half2* A2,
                                            const __half2* W1, const __half2* W2,
                                            int m0, int j0, int tid) {
    const __half2* Ap = (it < 16) ? A1 : A2;
    const __half2* Wp = (it < 16) ? W1 : W2;
    const int kk = (it & 15) << 4;
    const uint32_t as = sb + s * STAGE_B;
    const uint32_t ws = as + OFF_W;
    {   // A: 64 rows x 4 chunks, 1/thread
        int row = tid >> 2, u = tid & 3;
        CP_ASYNC16(as + (row << 6) + (u << 4),
                   Ap + (size_t)(m0 + row) * 256 + kk + u * 4);
    }
#pragma unroll
    for (int t2 = 0; t2 < 2; t2++) {    // W: 128 rows x 4 chunks, 2/thread
        int idx = tid + t2 * 256;
        int r = idx >> 2, u = idx & 3;
        int grow = (r & 3) * 512 + j0 + (r >> 2);
        CP_ASYNC16(ws + (r << 6) + (u << 4),
                   Wp + (size_t)grow * 256 + kk + u * 4);
    }
}

__global__ __launch_bounds__(256, 2) void lstm_persistent(
    const float* __restrict__ b_ih, const float* __restrict__ b_hh,
    const float* __restrict__ Wih32, const float* __restrict__ Whh32,
    float* __restrict__ out)
{
    extern __shared__ char smem[];
    const int cta = blockIdx.x;
    const int tid = threadIdx.x;

    // ---------------- converter CTAs: free-running, paced <=6 steps ahead ----------------
    if (cta >= NJOB) {
        const int w = cta - NJOB;
        for (int s = 2; s < NSTEPS; s++) {
            if (tid == 0 && s >= 6) spin_ge(&g_arr_l0[s - 6], 128);
            __syncthreads();
            const float* cIh = Wih32 + (size_t)(s * 2) * WSZF;
            const float* cHh = Whh32 + (size_t)(s * 2) * WSZF;
            __half2* dIh = g_w16ih + (size_t)(s * 2) * WPL2;
            __half2* dHh = g_w16hh + (size_t)(s * 2) * WPL2;
            for (int c = w * 256 + tid; c < 2 * CHUNKS_PER_TENSOR; c += NCONV * 256) {
                if (c < CHUNKS_PER_TENSOR) convert_chunk(cIh, dIh, c);
                else                       convert_chunk(cHh, dHh, c - CHUNKS_PER_TENSOR);
            }
            __threadfence();
            __syncthreads();
            if (tid == 0) atomicAdd(&g_arr_cv[s], 1);
        }
        return;
    }

    // ---------------- job CTAs: fixed (layer, tile) for all steps ----------------
    const uint32_t sb = smem_u32(smem);
    const int layer = (cta < 128) ? 0 : 1;
    const int tile = cta & 127;
    const int m0 = (tile >> 4) * 64;
    const int j0 = (tile & 15) * 32;

    const int lane = tid & 31, wid = tid >> 5;
    const int wm = wid & 1;          // 2 m-groups x 32 rows
    const int wn = wid >> 1;         // 4 n-groups x 8 jj
    const int r4 = lane >> 2, u = lane & 3;
    const bool evn = !(u & 1);

    float* smc = (float*)(smem + SMC_OFF);   // c tile, resident across all phases
    float* smb = (float*)(smem + BIAS_OFF);
    float* smh = (float*)smem;               // overlays stage region in epilogue

    for (int i = tid; i < 64 * CPAD; i += 256) smc[i] = 0.f;
    __syncthreads();

    const int aoff = ((wm * 32 + r4) << 6) + (u << 4);
    const int boff = ((wn * 32 + r4) << 6) + (u << 4) + OFF_W;

    for (int t = 0; t < NSTEPS; t++) {
        // ---- dependency-exact waits ----
        if (tid == 0) {
            if (layer == 0) {
                if (t >= 1) spin_ge(&g_arr_l0[t - 1], 128);   // h(l0,t-1) published
                if (t >= 2) spin_ge(&g_arr_l1[t - 2], 128);   // plane-reuse back-pressure
            } else {
                spin_ge(&g_arr_l0[t], 128);                   // h(l0,t) published
                if (t >= 1) spin_ge(&g_arr_l1[t - 1], 128);   // h(l1,t-1) published
            }
            spin_ge(&g_arr_cv[t], NCONV);                     // weights step t converted
            __threadfence();                                  // acquire
        }
        __syncthreads();

        const int wp = t & 1, rp = wp ^ 1;
        const __half2 *A1, *A2;
        if (layer == 0) {
            int xt = (t < NSTEPS - 1) ? t : NSTEPS - 2;  // source bug: step 29 reuses x[28]
            A1 = g_x16 + (size_t)xt * BH2;
            A2 = g_h16 + (size_t)(rp * 2 + 0) * BH2;
        } else {
            A1 = g_h16 + (size_t)(wp * 2 + 0) * BH2;
            A2 = g_h16 + (size_t)(rp * 2 + 1) * BH2;
        }
        const int widx = t * 2 + layer;
        const __half2* W1 = g_w16ih + (size_t)widx * WPL2;
        const __half2* W2 = g_w16hh + (size_t)widx * WPL2;
        __half2* h16o = g_h16 + (size_t)(wp * 2 + layer) * BH2;
        float* y   = (layer == 1) ? out + (size_t)t * BH : nullptr;
        float* h32 = (t == NSTEPS - 1) ? out + (size_t)(NSTEPS + layer) * BH : nullptr;

        if (tid < 128) {   // guard load-bearing: smb is 128 floats
            int g = tid >> 5, jj = tid & 31;
            smb[tid] = b_ih[(size_t)widx * GDIM + g * 512 + j0 + jj]
                     + b_hh[(size_t)widx * GDIM + g * 512 + j0 + jj];
        }

        float acc[2][4][4];
#pragma unroll
        for (int mt = 0; mt < 2; mt++)
#pragma unroll
            for (int nt = 0; nt < 4; nt++)
#pragma unroll
                for (int e = 0; e < 4; e++) acc[mt][nt][e] = 0.f;

        issue_stage(sb, 0, 0, A1, A2, W1, W2, m0, j0, tid);
        issue_stage(sb, 1, 1, A1, A2, W1, W2, m0, j0, tid); CP_COMMIT();
        issue_stage(sb, 2, 2, A1, A2, W1, W2, m0, j0, tid);
        issue_stage(sb, 3, 3, A1, A2, W1, W2, m0, j0, tid); CP_COMMIT();

        int s = 0;
        for (int itp = 0; itp < NKB; itp += 2) {
            CP_WAIT1();
            __syncthreads();
            if (itp + 4 < NKB) {
                int s4 = s + 4; if (s4 >= NSTAGE) s4 -= NSTAGE;
                int s5 = s4 + 1; if (s5 >= NSTAGE) s5 -= NSTAGE;
                issue_stage(sb, s4, itp + 4, A1, A2, W1, W2, m0, j0, tid);
                issue_stage(sb, s5, itp + 5, A1, A2, W1, W2, m0, j0, tid);
            }
            CP_COMMIT();

#pragma unroll
            for (int h = 0; h < 2; h++) {
                const char* st = smem + (s + h) * STAGE_B;
                uint4 a0lo = *(const uint4*)(st + aoff);
                uint4 a0hi = *(const uint4*)(st + aoff + 512);
                uint4 a1lo = *(const uint4*)(st + aoff + 1024);
                uint4 a1hi = *(const uint4*)(st + aoff + 1536);
#pragma unroll
                for (int nt = 0; nt < 4; nt++) {
                    uint4 bb = *(const uint4*)(st + boff + (nt << 9));
                    mma_f16(acc[0][nt], a0lo.x, a0hi.x, a0lo.y, a0hi.y, bb.x, bb.y);
                    mma_f16(acc[0][nt], a0lo.z, a0hi.z, a0lo.w, a0hi.w, bb.z, bb.w);
                    mma_f16(acc[1][nt], a1lo.x, a1hi.x, a1lo.y, a1hi.y, bb.x, bb.y);
                    mma_f16(acc[1][nt], a1lo.z, a1hi.z, a1lo.w, a1hi.w, bb.z, bb.w);
                }
            }
            s += 2; if (s == NSTAGE) s = 0;
        }

        // ---- fused LSTM cell epilogue (c resident in smem) ----
        __syncthreads();
#pragma unroll
        for (int mt = 0; mt < 2; mt++) {
            const int row = wm * 32 + mt * 16 + r4 + (evn ? 0 : 8);
#pragma unroll
            for (int nt = 0; nt < 4; nt++) {
                float x0 = __shfl_xor_sync(0xFFFFFFFFu, acc[mt][nt][0], 1);
                float x1 = __shfl_xor_sync(0xFFFFFFFFu, acc[mt][nt][1], 1);
                float x2 = __shfl_xor_sync(0xFFFFFFFFu, acc[mt][nt][2], 1);
                float x3 = __shfl_xor_sync(0xFFFFFFFFu, acc[mt][nt][3], 1);
                int jj = wn * 8 + nt * 2 + (u >> 1);
                float vi = (evn ? acc[mt][nt][0] : x2) + smb[jj];
                float vf = (evn ? acc[mt][nt][1] : x3) + smb[32 + jj];
                float vg = (evn ? x0 : acc[mt][nt][2]) + smb[64 + jj];
                float vo = (evn ? x1 : acc[mt][nt][3]) + smb[96 + jj];
                float ii = fast_sigmoid(vi);
                float ff = fast_sigmoid(vf);
                float gg = fast_tanh(vg);
                float oo = fast_sigmoid(vo);
                float cn = ff * smc[row * CPAD + jj] + ii * gg;
                float hn = oo * fast_tanh(cn);
                smc[row * CPAD + jj] = cn;
                smh[row * CPAD + jj] = hn;
            }
        }
        __syncthreads();

        // ---- CRITICAL-CHAIN stores first: h16 (the only thing consumers read) ----
        for (int i = tid; i < 64 * 16; i += 256) {
            int r = i >> 4, q = i & 15;
            int pq = (q & 3) * 4 + (q >> 2);
            __half2 hv = __floats2half2_rn(smh[r * CPAD + 2 * q], smh[r * CPAD + 2 * q + 1]);
            h16o[(size_t)(m0 + r) * 256 + (j0 >> 1) + pq] = hv;
        }

        // ---- publish (release) ASAP ----
        __threadfence();
        __syncthreads();
        if (tid == 0) atomicAdd(layer == 0 ? &g_arr_l0[t] : &g_arr_l1[t], 1);

        // ---- off-chain stores: y / h32 (write-once, evict-first) ----
        if (y || h32) {
            for (int i = tid; i < 64 * 32; i += 256) {
                int r = i >> 5, jj = i & 31;
                size_t g = (size_t)(m0 + r) * HDIM + j0 + jj;
                float hv = smh[r * CPAD + jj];
                if (y)   stg_cs(y + g,   hv);
                if (h32) stg_cs(h32 + g, hv);
            }
        }
        // smh/smc are only re-read by THIS cta before its next-phase stage writes -> safe
    }

    // final c -> output tail
    float* cdst = out + (size_t)(NSTEPS + 2 + layer) * BH;
    for (int i = tid; i < 64 * 32; i += 256) {
        int r = i >> 5, jj = i & 31;
        stg_cs(cdst + (size_t)(m0 + r) * HDIM + j0 + jj, smc[r * CPAD + jj]);
    }
}

// upfront conversions
__global__ __launch_bounds__(256) void conv_chunks(const float* __restrict__ src,
                                                   __half2* __restrict__ dst, int nChunks) {
    int c = blockIdx.x * 256 + threadIdx.x;
    if (c < nChunks) convert_chunk(src, dst, c);
}

__global__ void zero_state() {
    int i = blockIdx.x * 256 + threadIdx.x;
    if (i < 2 * BH2) g_h16[2 * BH2 + i] = __floats2half2_rn(0.f, 0.f);  // parity-1 planes
    if (i < NSTEPS) {
        g_arr_l0[i] = 0;
        g_arr_l1[i] = 0;
        g_arr_cv[i] = (i < 2) ? NCONV : 0;   // steps 0,1 converted upfront
    }
}

// ---------------- host ----------------
extern "C" void kernel_launch(void* const* d_in, const int* in_sizes, int n_in,
                              void* d_out, int out_size)
{
    const float* x    = (const float*)d_in[0];
    const float* W_ih = (const float*)d_in[1];
    const float* W_hh = (const float*)d_in[2];
    const float* b_ih = (const float*)d_in[3];
    const float* b_hh = (const float*)d_in[4];
    float* out = (float*)d_out;

    __half2 *w16ih, *w16hh, *x16;
    cudaGetSymbolAddress((void**)&w16ih, g_w16ih);
    cudaGetSymbolAddress((void**)&w16hh, g_w16hh);
    cudaGetSymbolAddress((void**)&x16,   g_x16);

    cudaFuncSetAttribute(lstm_persistent, cudaFuncAttributeMaxDynamicSharedMemorySize, SMEM_BYTES);

    conv_chunks<<<(NSTEPS * 512 * 16 + 255) / 256, 256>>>(x, x16, NSTEPS * 512 * 16);
    conv_chunks<<<(2 * CHUNKS_PER_TENSOR + 255) / 256, 256>>>(W_ih, w16ih, 2 * CHUNKS_PER_TENSOR);
    conv_chunks<<<(2 * CHUNKS_PER_TENSOR + 255) / 256, 256>>>(W_hh, w16hh, 2 * CHUNKS_PER_TENSOR);
    zero_state<<<(2 * BH2 + 255) / 256, 256>>>();

    lstm_persistent<<<NCTAS, 256, SMEM_BYTES>>>(b_ih, b_hh, W_ih, W_hh, out);
}

// round 16
// speedup vs baseline: 1.0338x; 1.0246x over previous
#include <cuda_runtime.h>
#include <cuda_fp16.h>
#include <cstdint>
#include <math.h>

#define HDIM   512
#define BDIM   512
#define GDIM   2048
#define NSTEPS 30
#define BH     (BDIM * HDIM)
#define BH2    (BDIM * 256)          // half2 per [512,512] plane
#define WPL2   (2048 * 256)          // half2 per [2048,512] weight plane
#define WSZF   ((size_t)GDIM * HDIM) // fp32 weight plane elems

__device__ __align__(1024) __half2 g_w16ih[60 * WPL2];   // 125.8 MB
__device__ __align__(1024) __half2 g_w16hh[60 * WPL2];   // 125.8 MB
__device__ __align__(1024) __half2 g_x16[NSTEPS * BH2];  // 15.7 MB
__device__ __align__(1024) __half2 g_h16[4 * BH2];       // [parity][layer], 2 MB

// dependency-exact sync counters (zeroed every replay by zero_state)
__device__ int g_arr_l0[NSTEPS];
__device__ int g_arr_l1[NSTEPS];
__device__ int g_arr_cv[NSTEPS];

#define NJOB  256
#define NCONV 40
#define NCTAS (NJOB + NCONV)        // 296 = 2/SM x 148 SMs (all co-resident)

// ---------------- helpers ----------------
__device__ __forceinline__ uint32_t smem_u32(const void* p) {
    uint32_t a;
    asm("{ .reg .u64 t; cvta.to.shared.u64 t, %1; cvt.u32.u64 %0, t; }" : "=r"(a) : "l"(p));
    return a;
}
#define CP_ASYNC16(dst_u32, src_ptr) \
    asm volatile("cp.async.cg.shared.global [%0], [%1], 16;" \
                 :: "r"(dst_u32), "l"(src_ptr) : "memory")
#define CP_COMMIT() asm volatile("cp.async.commit_group;" ::: "memory")
#define CP_WAIT1()  asm volatile("cp.async.wait_group 1;" ::: "memory")

__device__ __forceinline__ void stg_cs(float* p, float v) {
    asm volatile("st.global.cs.f32 [%0], %1;" :: "l"(p), "f"(v) : "memory");
}

__device__ __forceinline__ void mma_f16(float* d,
                                        uint32_t a0, uint32_t a1, uint32_t a2, uint32_t a3,
                                        uint32_t b0, uint32_t b1) {
    asm volatile(
        "mma.sync.aligned.m16n8k16.row.col.f32.f16.f16.f32 "
        "{%0,%1,%2,%3}, {%4,%5,%6,%7}, {%8,%9}, {%0,%1,%2,%3};"
        : "+f"(d[0]), "+f"(d[1]), "+f"(d[2]), "+f"(d[3])
        : "r"(a0), "r"(a1), "r"(a2), "r"(a3), "r"(b0), "r"(b1));
}

// single-MUFU activations (tanh.approx.f32, sm_75+ base-target legal)
__device__ __forceinline__ float tanh_fast(float x) {
    float r;
    asm("tanh.approx.f32 %0, %1;" : "=f"(r) : "f"(x));
    return r;
}
__device__ __forceinline__ float sigmoid_fast(float x) {
    return fmaf(0.5f, tanh_fast(0.5f * x), 0.5f);
}

__device__ __forceinline__ uint32_t pk(float a, float b) {
    __half2 h = __floats2half2_rn(a, b);
    return *reinterpret_cast<uint32_t*>(&h);
}
__device__ __forceinline__ void spin_ge(volatile int* p, int target) {
    while (*p < target) __nanosleep(32);
}

// ---------------- vectorized fp32 -> permuted fp16 chunk converter ----------------
__device__ __forceinline__ void convert_chunk(const float* __restrict__ src,
                                              __half2* __restrict__ dst, int c) {
    const int row = c >> 4, cb = c & 15;
    const float4* s4 = (const float4*)(src + ((size_t)row << 9) + (cb << 5));
    float f[32];
#pragma unroll
    for (int q = 0; q < 8; q++) {
        float4 v = s4[q];
        f[q * 4 + 0] = v.x; f[q * 4 + 1] = v.y; f[q * 4 + 2] = v.z; f[q * 4 + 3] = v.w;
    }
    uint32_t o[16];
#pragma unroll
    for (int p = 0; p < 16; p++) {
        int q = (p & 3) * 4 + (p >> 2);
        o[p] = pk(f[2 * q], f[2 * q + 1]);
    }
    uint4* d4 = (uint4*)(dst + ((size_t)row << 8) + (cb << 4));
#pragma unroll
    for (int v = 0; v < 4; v++)
        d4[v] = make_uint4(o[v * 4], o[v * 4 + 1], o[v * 4 + 2], o[v * 4 + 3]);
}

// ---------------- smem layout (R11/R13-proven) ----------------
#define NSTAGE    6
#define STAGE_B   12288
#define OFF_W     4096
#define SMC_OFF   (NSTAGE * STAGE_B)        // 73728: c tile [64][36] floats
#define BIAS_OFF  (SMC_OFF + 64 * 36 * 4)   // 82944
#define SMEM_BYTES (BIAS_OFF + 512)         // 83456
#define NKB 32
#define CPAD 36
#define CHUNKS_PER_TENSOR 65536

__device__ __forceinline__ void issue_stage(uint32_t sb, int s, int it,
                                            const __half2* A1, const __half2* A2,
                                            const __half2* W1, const __half2* W2,
                                            int m0, int j0, int tid) {
    const __half2* Ap = (it < 16) ? A1 : A2;
    const __half2* Wp = (it < 16) ? W1 : W2;
    const int kk = (it & 15) << 4;
    const uint32_t as = sb + s * STAGE_B;
    const uint32_t ws = as + OFF_W;
    {   // A: 64 rows x 4 chunks, 1/thread
        int row = tid >> 2, u = tid & 3;
        CP_ASYNC16(as + (row << 6) + (u << 4),
                   Ap + (size_t)(m0 + row) * 256 + kk + u * 4);
    }
#pragma unroll
    for (int t2 = 0; t2 < 2; t2++) {    // W: 128 rows x 4 chunks, 2/thread
        int idx = tid + t2 * 256;
        int r = idx >> 2, u = idx & 3;
        int grow = (r & 3) * 512 + j0 + (r >> 2);
        CP_ASYNC16(ws + (r << 6) + (u << 4),
                   Wp + (size_t)grow * 256 + kk + u * 4);
    }
}

__global__ __launch_bounds__(256, 2) void lstm_persistent(
    const float* __restrict__ b_ih, const float* __restrict__ b_hh,
    const float* __restrict__ Wih32, const float* __restrict__ Whh32,
    float* __restrict__ out)
{
    extern __shared__ char smem[];
    const int cta = blockIdx.x;
    const int tid = threadIdx.x;

    // ---------------- converter CTAs: free-running, paced <=6 steps ahead ----------------
    if (cta >= NJOB) {
        const int w = cta - NJOB;
        for (int s = 2; s < NSTEPS; s++) {
            if (tid == 0 && s >= 6) spin_ge(&g_arr_l0[s - 6], 128);
            __syncthreads();
            const float* cIh = Wih32 + (size_t)(s * 2) * WSZF;
            const float* cHh = Whh32 + (size_t)(s * 2) * WSZF;
            __half2* dIh = g_w16ih + (size_t)(s * 2) * WPL2;
            __half2* dHh = g_w16hh + (size_t)(s * 2) * WPL2;
            for (int c = w * 256 + tid; c < 2 * CHUNKS_PER_TENSOR; c += NCONV * 256) {
                if (c < CHUNKS_PER_TENSOR) convert_chunk(cIh, dIh, c);
                else                       convert_chunk(cHh, dHh, c - CHUNKS_PER_TENSOR);
            }
            __threadfence();
            __syncthreads();
            if (tid == 0) atomicAdd(&g_arr_cv[s], 1);
        }
        return;
    }

    // ---------------- job CTAs: fixed (layer, tile) for all steps ----------------
    const uint32_t sb = smem_u32(smem);
    const int layer = (cta < 128) ? 0 : 1;
    const int tile = cta & 127;
    const int m0 = (tile >> 4) * 64;
    const int j0 = (tile & 15) * 32;

    const int lane = tid & 31, wid = tid >> 5;
    const int wm = wid & 1;          // 2 m-groups x 32 rows
    const int wn = wid >> 1;         // 4 n-groups x 8 jj
    const int r4 = lane >> 2, u = lane & 3;
    const bool evn = !(u & 1);

    float* smc = (float*)(smem + SMC_OFF);   // c tile, resident across all phases
    float* smb = (float*)(smem + BIAS_OFF);
    float* smh = (float*)smem;               // overlays stage region in epilogue

    for (int i = tid; i < 64 * CPAD; i += 256) smc[i] = 0.f;
    __syncthreads();

    const int aoff = ((wm * 32 + r4) << 6) + (u << 4);
    const int boff = ((wn * 32 + r4) << 6) + (u << 4) + OFF_W;

    for (int t = 0; t < NSTEPS; t++) {
        // ---- dependency-exact waits ----
        if (tid == 0) {
            if (layer == 0) {
                if (t >= 1) spin_ge(&g_arr_l0[t - 1], 128);   // h(l0,t-1) published
                if (t >= 2) spin_ge(&g_arr_l1[t - 2], 128);   // plane-reuse back-pressure
            } else {
                spin_ge(&g_arr_l0[t], 128);                   // h(l0,t) published
                if (t >= 1) spin_ge(&g_arr_l1[t - 1], 128);   // h(l1,t-1) published
            }
            spin_ge(&g_arr_cv[t], NCONV);                     // weights step t converted
            __threadfence();                                  // acquire
        }
        __syncthreads();

        const int wp = t & 1, rp = wp ^ 1;
        const __half2 *A1, *A2;
        if (layer == 0) {
            int xt = (t < NSTEPS - 1) ? t : NSTEPS - 2;  // source bug: step 29 reuses x[28]
            A1 = g_x16 + (size_t)xt * BH2;
            A2 = g_h16 + (size_t)(rp * 2 + 0) * BH2;
        } else {
            A1 = g_h16 + (size_t)(wp * 2 + 0) * BH2;
            A2 = g_h16 + (size_t)(rp * 2 + 1) * BH2;
        }
        const int widx = t * 2 + layer;
        const __half2* W1 = g_w16ih + (size_t)widx * WPL2;
        const __half2* W2 = g_w16hh + (size_t)widx * WPL2;
        __half2* h16o = g_h16 + (size_t)(wp * 2 + layer) * BH2;
        float* y   = (layer == 1) ? out + (size_t)t * BH : nullptr;
        float* h32 = (t == NSTEPS - 1) ? out + (size_t)(NSTEPS + layer) * BH : nullptr;

        if (tid < 128) {   // guard load-bearing: smb is 128 floats
            int g = tid >> 5, jj = tid & 31;
            smb[tid] = b_ih[(size_t)widx * GDIM + g * 512 + j0 + jj]
                     + b_hh[(size_t)widx * GDIM + g * 512 + j0 + jj];
        }

        float acc[2][4][4];
#pragma unroll
        for (int mt = 0; mt < 2; mt++)
#pragma unroll
            for (int nt = 0; nt < 4; nt++)
#pragma unroll
                for (int e = 0; e < 4; e++) acc[mt][nt][e] = 0.f;

        issue_stage(sb, 0, 0, A1, A2, W1, W2, m0, j0, tid);
        issue_stage(sb, 1, 1, A1, A2, W1, W2, m0, j0, tid); CP_COMMIT();
        issue_stage(sb, 2, 2, A1, A2, W1, W2, m0, j0, tid);
        issue_stage(sb, 3, 3, A1, A2, W1, W2, m0, j0, tid); CP_COMMIT();

        int s = 0;
        for (int itp = 0; itp < NKB; itp += 2) {
            CP_WAIT1();
            __syncthreads();
            if (itp + 4 < NKB) {
                int s4 = s + 4; if (s4 >= NSTAGE) s4 -= NSTAGE;
                int s5 = s4 + 1; if (s5 >= NSTAGE) s5 -= NSTAGE;
                issue_stage(sb, s4, itp + 4, A1, A2, W1, W2, m0, j0, tid);
                issue_stage(sb, s5, itp + 5, A1, A2, W1, W2, m0, j0, tid);
            }
            CP_COMMIT();

#pragma unroll
            for (int h = 0; h < 2; h++) {
                const char* st = smem + (s + h) * STAGE_B;
                uint4 a0lo = *(const uint4*)(st + aoff);
                uint4 a0hi = *(const uint4*)(st + aoff + 512);
                uint4 a1lo = *(const uint4*)(st + aoff + 1024);
                uint4 a1hi = *(const uint4*)(st + aoff + 1536);
#pragma unroll
                for (int nt = 0; nt < 4; nt++) {
                    uint4 bb = *(const uint4*)(st + boff + (nt << 9));
                    mma_f16(acc[0][nt], a0lo.x, a0hi.x, a0lo.y, a0hi.y, bb.x, bb.y);
                    mma_f16(acc[0][nt], a0lo.z, a0hi.z, a0lo.w, a0hi.w, bb.z, bb.w);
                    mma_f16(acc[1][nt], a1lo.x, a1hi.x, a1lo.y, a1hi.y, bb.x, bb.y);
                    mma_f16(acc[1][nt], a1lo.z, a1hi.z, a1lo.w, a1hi.w, bb.z, bb.w);
                }
            }
            s += 2; if (s == NSTAGE) s = 0;
        }

        // ---- fused LSTM cell epilogue (c resident in smem) ----
        __syncthreads();
#pragma unroll
        for (int mt = 0; mt < 2; mt++) {
            const int row = wm * 32 + mt * 16 + r4 + (evn ? 0 : 8);
#pragma unroll
            for (int nt = 0; nt < 4; nt++) {
                float x0 = __shfl_xor_sync(0xFFFFFFFFu, acc[mt][nt][0], 1);
                float x1 = __shfl_xor_sync(0xFFFFFFFFu, acc[mt][nt][1], 1);
                float x2 = __shfl_xor_sync(0xFFFFFFFFu, acc[mt][nt][2], 1);
                float x3 = __shfl_xor_sync(0xFFFFFFFFu, acc[mt][nt][3], 1);
                int jj = wn * 8 + nt * 2 + (u >> 1);
                float vi = (evn ? acc[mt][nt][0] : x2) + smb[jj];
                float vf = (evn ? acc[mt][nt][1] : x3) + smb[32 + jj];
                float vg = (evn ? x0 : acc[mt][nt][2]) + smb[64 + jj];
                float vo = (evn ? x1 : acc[mt][nt][3]) + smb[96 + jj];
                float ii = sigmoid_fast(vi);
                float ff = sigmoid_fast(vf);
                float gg = tanh_fast(vg);
                float oo = sigmoid_fast(vo);
                float cn = ff * smc[row * CPAD + jj] + ii * gg;
                float hn = oo * tanh_fast(cn);
                smc[row * CPAD + jj] = cn;
                smh[row * CPAD + jj] = hn;
            }
        }
        __syncthreads();

        // ---- CRITICAL-CHAIN stores first: h16 (the only thing consumers read) ----
        for (int i = tid; i < 64 * 16; i += 256) {
            int r = i >> 4, q = i & 15;
            int pq = (q & 3) * 4 + (q >> 2);
            __half2 hv = __floats2half2_rn(smh[r * CPAD + 2 * q], smh[r * CPAD + 2 * q + 1]);
            h16o[(size_t)(m0 + r) * 256 + (j0 >> 1) + pq] = hv;
        }

        // ---- publish (release) ASAP ----
        __threadfence();
        __syncthreads();
        if (tid == 0) atomicAdd(layer == 0 ? &g_arr_l0[t] : &g_arr_l1[t], 1);

        // ---- off-chain stores: y / h32 (write-once, evict-first) ----
        if (y || h32) {
            for (int i = tid; i < 64 * 32; i += 256) {
                int r = i >> 5, jj = i & 31;
                size_t g = (size_t)(m0 + r) * HDIM + j0 + jj;
                float hv = smh[r * CPAD + jj];
                if (y)   stg_cs(y + g,   hv);
                if (h32) stg_cs(h32 + g, hv);
            }
        }
        // smh/smc are only re-read by THIS cta before its next-phase stage writes -> safe
    }

    // final c -> output tail
    float* cdst = out + (size_t)(NSTEPS + 2 + layer) * BH;
    for (int i = tid; i < 64 * 32; i += 256) {
        int r = i >> 5, jj = i & 31;
        stg_cs(cdst + (size_t)(m0 + r) * HDIM + j0 + jj, smc[r * CPAD + jj]);
    }
}

// upfront conversions
__global__ __launch_bounds__(256) void conv_chunks(const float* __restrict__ src,
                                                   __half2* __restrict__ dst, int nChunks) {
    int c = blockIdx.x * 256 + threadIdx.x;
    if (c < nChunks) convert_chunk(src, dst, c);
}

__global__ void zero_state() {
    int i = blockIdx.x * 256 + threadIdx.x;
    if (i < 2 * BH2) g_h16[2 * BH2 + i] = __floats2half2_rn(0.f, 0.f);  // parity-1 planes
    if (i < NSTEPS) {
        g_arr_l0[i] = 0;
        g_arr_l1[i] = 0;
        g_arr_cv[i] = (i < 2) ? NCONV : 0;   // steps 0,1 converted upfront
    }
}

// ---------------- host ----------------
extern "C" void kernel_launch(void* const* d_in, const int* in_sizes, int n_in,
                              void* d_out, int out_size)
{
    const float* x    = (const float*)d_in[0];
    const float* W_ih = (const float*)d_in[1];
    const float* W_hh = (const float*)d_in[2];
    const float* b_ih = (const float*)d_in[3];
    const float* b_hh = (const float*)d_in[4];
    float* out = (float*)d_out;

    __half2 *w16ih, *w16hh, *x16;
    cudaGetSymbolAddress((void**)&w16ih, g_w16ih);
    cudaGetSymbolAddress((void**)&w16hh, g_w16hh);
    cudaGetSymbolAddress((void**)&x16,   g_x16);

    cudaFuncSetAttribute(lstm_persistent, cudaFuncAttributeMaxDynamicSharedMemorySize, SMEM_BYTES);

    conv_chunks<<<(NSTEPS * 512 * 16 + 255) / 256, 256>>>(x, x16, NSTEPS * 512 * 16);
    conv_chunks<<<(2 * CHUNKS_PER_TENSOR + 255) / 256, 256>>>(W_ih, w16ih, 2 * CHUNKS_PER_TENSOR);
    conv_chunks<<<(2 * CHUNKS_PER_TENSOR + 255) / 256, 256>>>(W_hh, w16hh, 2 * CHUNKS_PER_TENSOR);
    zero_state<<<(2 * BH2 + 255) / 256, 256>>>();

    lstm_persistent<<<NCTAS, 256, SMEM_BYTES>>>(b_ih, b_hh, W_ih, W_hh, out);
}